// round 3
// baseline (speedup 1.0000x reference)
#include <cuda_runtime.h>
#include <math.h>

#define MAX_RAYS 65536
__device__ int g_seg[MAX_RAYS + 1];

typedef unsigned long long ull;

// ---- packed f32x2 helpers (Blackwell) -------------------------------------
__device__ __forceinline__ ull f2fma(ull a, ull b, ull c) {
    ull d;
    asm("fma.rn.f32x2 %0, %1, %2, %3;" : "=l"(d) : "l"(a), "l"(b), "l"(c));
    return d;
}
__device__ __forceinline__ ull f2add(ull a, ull b) {
    ull d;
    asm("add.rn.f32x2 %0, %1, %2;" : "=l"(d) : "l"(a), "l"(b));
    return d;
}
__device__ __forceinline__ ull f2pack(float lo, float hi) {
    ull d;
    asm("mov.b64 %0, {%1, %2};" : "=l"(d) : "f"(lo), "f"(hi));
    return d;
}
__device__ __forceinline__ void f2unpack(ull v, float& lo, float& hi) {
    asm("mov.b64 {%0, %1}, %2;" : "=f"(lo), "=f"(hi) : "l"(v));
}
#define ABSMASK 0x7FFFFFFF7FFFFFFFULL

// ---------------------------------------------------------------------------
// Kernel A: segment starts from sorted ray_indices (searchsorted).
// ---------------------------------------------------------------------------
__global__ void seg_boundary_kernel(const int* __restrict__ ri, int S, int n_rays) {
    int i = blockIdx.x * blockDim.x + threadIdx.x;
    if (i >= S) return;
    int r = ri[i];
    int rp = (i == 0) ? -1 : ri[i - 1];
    for (int rr = rp + 1; rr <= r; ++rr) g_seg[rr] = i;
    if (i == S - 1) {
        for (int rr = r + 1; rr <= n_rays; ++rr) g_seg[rr] = S;
    }
}

// ---------------------------------------------------------------------------
// Kernel B: one warp per ray; 64-sample chunks (2 samples/lane) so each
// broadcast weight load feeds two f32x2 MLP evaluations.
// ---------------------------------------------------------------------------
struct SampleIn  { ull px2, py2, pz2; float tm, dt; bool valid; };

__global__ void __launch_bounds__(256, 2) render_kernel(
    const float* __restrict__ rays_o,
    const float* __restrict__ rays_d,
    const float* __restrict__ W1,
    const float* __restrict__ b1,
    const float* __restrict__ W2,
    const float* __restrict__ b2,
    const float* __restrict__ t_starts,
    const float* __restrict__ t_ends,
    float* __restrict__ out,
    int n_rays)
{
    __shared__ ulonglong2 sA[32];   // {wx2, wy2}
    __shared__ ulonglong2 sB[32];   // {wz2, b1_2}
    __shared__ ull        sC[32];   // 0.5*w2_2

    if (threadIdx.x < 32) {
        const int p = threadIdx.x;
        const int j = 2 * p;
        ulonglong2 A, B;
        A.x = f2pack(W1[j],       W1[j + 1]);
        A.y = f2pack(W1[64 + j],  W1[64 + j + 1]);
        B.x = f2pack(W1[128 + j], W1[128 + j + 1]);
        B.y = f2pack(b1[j],       b1[j + 1]);
        sA[p] = A;
        sB[p] = B;
        sC[p] = f2pack(0.5f * W2[j], 0.5f * W2[j + 1]);
    }
    __syncthreads();
    const float b2v = __ldg(b2);

    const int warp_id = (blockIdx.x * blockDim.x + threadIdx.x) >> 5;
    const int lane    = threadIdx.x & 31;
    if (warp_id >= n_rays) return;
    const int r = warp_id;

    const int start = g_seg[r];
    const int end   = g_seg[r + 1];

    const float ox = __ldg(&rays_o[3 * r    ]);
    const float oy = __ldg(&rays_o[3 * r + 1]);
    const float oz = __ldg(&rays_o[3 * r + 2]);
    const float dx = __ldg(&rays_d[3 * r    ]);
    const float dy = __ldg(&rays_d[3 * r + 1]);
    const float dz = __ldg(&rays_d[3 * r + 2]);

    float carry = 0.f;
    float opac  = 0.f;
    float dnum  = 0.f;

    for (int i0 = start; i0 < end; i0 += 64) {
        // ---- gather two samples per lane (clamped loads, masked results) ---
        SampleIn smp[2];
        #pragma unroll
        for (int k = 0; k < 2; ++k) {
            const int  i     = i0 + 32 * k + lane;
            const bool valid = (i < end);
            const int  ic    = valid ? i : (end - 1);
            const float ts = t_starts[ic];
            const float te = t_ends[ic];
            const float tm = 0.5f * (ts + te);
            const float px = fmaf(dx, tm, ox);
            const float py = fmaf(dy, tm, oy);
            const float pz = fmaf(dz, tm, oz);
            smp[k].px2 = f2pack(px, px);
            smp[k].py2 = f2pack(py, py);
            smp[k].pz2 = f2pack(pz, pz);
            smp[k].tm  = valid ? tm : 0.f;
            smp[k].dt  = te - ts;
            smp[k].valid = valid;
        }
        const bool anyB = (i0 + 32 < end);   // uniform across warp

        float sv[2];   // s = softplus(mlp)*dt per sub-sample

        if (anyB) {
            // joint pair loop: each weight load feeds both samples
            ull acA0 = 0ull, acA1 = 0ull, acB0 = 0ull, acB1 = 0ull;
            #pragma unroll
            for (int p = 0; p < 32; p += 2) {
                {
                    const ulonglong2 A = sA[p];
                    const ulonglong2 B = sB[p];
                    const ull        C = sC[p];
                    ull hA = f2fma(smp[0].pz2, B.x, B.y);
                    ull hB = f2fma(smp[1].pz2, B.x, B.y);
                    hA = f2fma(smp[0].py2, A.y, hA);
                    hB = f2fma(smp[1].py2, A.y, hB);
                    hA = f2fma(smp[0].px2, A.x, hA);
                    hB = f2fma(smp[1].px2, A.x, hB);
                    hA = f2add(hA, hA & ABSMASK);
                    hB = f2add(hB, hB & ABSMASK);
                    acA0 = f2fma(hA, C, acA0);
                    acB0 = f2fma(hB, C, acB0);
                }
                {
                    const ulonglong2 A = sA[p + 1];
                    const ulonglong2 B = sB[p + 1];
                    const ull        C = sC[p + 1];
                    ull hA = f2fma(smp[0].pz2, B.x, B.y);
                    ull hB = f2fma(smp[1].pz2, B.x, B.y);
                    hA = f2fma(smp[0].py2, A.y, hA);
                    hB = f2fma(smp[1].py2, A.y, hB);
                    hA = f2fma(smp[0].px2, A.x, hA);
                    hB = f2fma(smp[1].px2, A.x, hB);
                    hA = f2add(hA, hA & ABSMASK);
                    hB = f2add(hB, hB & ABSMASK);
                    acA1 = f2fma(hA, C, acA1);
                    acB1 = f2fma(hB, C, acB1);
                }
            }
            float lo, hi;
            f2unpack(f2add(acA0, acA1), lo, hi);
            const float accA = b2v + lo + hi;
            f2unpack(f2add(acB0, acB1), lo, hi);
            const float accB = b2v + lo + hi;
            const float spA = fmaxf(accA, 0.f) + __logf(1.f + __expf(-fabsf(accA)));
            const float spB = fmaxf(accB, 0.f) + __logf(1.f + __expf(-fabsf(accB)));
            sv[0] = smp[0].valid ? spA * smp[0].dt : 0.f;
            sv[1] = smp[1].valid ? spB * smp[1].dt : 0.f;
        } else {
            // A-only pair loop
            ull acA0 = 0ull, acA1 = 0ull;
            #pragma unroll
            for (int p = 0; p < 32; p += 2) {
                {
                    const ulonglong2 A = sA[p];
                    const ulonglong2 B = sB[p];
                    const ull        C = sC[p];
                    ull hA = f2fma(smp[0].pz2, B.x, B.y);
                    hA = f2fma(smp[0].py2, A.y, hA);
                    hA = f2fma(smp[0].px2, A.x, hA);
                    hA = f2add(hA, hA & ABSMASK);
                    acA0 = f2fma(hA, C, acA0);
                }
                {
                    const ulonglong2 A = sA[p + 1];
                    const ulonglong2 B = sB[p + 1];
                    const ull        C = sC[p + 1];
                    ull hA = f2fma(smp[0].pz2, B.x, B.y);
                    hA = f2fma(smp[0].py2, A.y, hA);
                    hA = f2fma(smp[0].px2, A.x, hA);
                    hA = f2add(hA, hA & ABSMASK);
                    acA1 = f2fma(hA, C, acA1);
                }
            }
            float lo, hi;
            f2unpack(f2add(acA0, acA1), lo, hi);
            const float accA = b2v + lo + hi;
            const float spA = fmaxf(accA, 0.f) + __logf(1.f + __expf(-fabsf(accA)));
            sv[0] = smp[0].valid ? spA * smp[0].dt : 0.f;
            sv[1] = 0.f;
        }

        // ---- segmented scan + accumulate, sub-chunk A then B ---------------
        #pragma unroll
        for (int k = 0; k < 2; ++k) {
            if (k == 1 && !anyB) break;
            const float s = sv[k];
            float incl = s;
            #pragma unroll
            for (int off = 1; off < 32; off <<= 1) {
                float v = __shfl_up_sync(0xffffffffu, incl, off);
                if (lane >= off) incl += v;
            }
            const float excl = incl - s;
            // invalid lanes: s==0, tm==0 -> w*tm==0 and w==exp(..)*0==0
            const float w = __expf(-(carry + excl)) * (-expm1f(-s));
            opac += w;
            dnum  = fmaf(w, smp[k].tm, dnum);
            carry += __shfl_sync(0xffffffffu, incl, 31);
        }
    }

    #pragma unroll
    for (int off = 16; off; off >>= 1) {
        opac += __shfl_xor_sync(0xffffffffu, opac, off);
        dnum += __shfl_xor_sync(0xffffffffu, dnum, off);
    }

    if (lane == 0) {
        const float depth = dnum / fmaxf(opac, 1.17549435e-38f);
        out[2 * r    ] = opac;
        out[2 * r + 1] = depth;
    }
}

extern "C" void kernel_launch(void* const* d_in, const int* in_sizes, int n_in,
                              void* d_out, int out_size) {
    const float* rays_o      = (const float*)d_in[0];
    const float* rays_d      = (const float*)d_in[1];
    const float* W1          = (const float*)d_in[2];
    const float* b1          = (const float*)d_in[3];
    const float* W2          = (const float*)d_in[4];
    const float* b2          = (const float*)d_in[5];
    const float* t_starts    = (const float*)d_in[6];
    const float* t_ends      = (const float*)d_in[7];
    const int*   ray_indices = (const int*)d_in[8];

    const int S      = in_sizes[6];
    const int n_rays = in_sizes[0] / 3;

    float* out = (float*)d_out;

    seg_boundary_kernel<<<(S + 255) / 256, 256>>>(ray_indices, S, n_rays);

    const int warps_per_block = 8;
    const int blocks = (n_rays + warps_per_block - 1) / warps_per_block;
    render_kernel<<<blocks, warps_per_block * 32>>>(
        rays_o, rays_d, W1, b1, W2, b2, t_starts, t_ends, out, n_rays);
}

// round 5
// speedup vs baseline: 3.0149x; 3.0149x over previous
#include <cuda_runtime.h>
#include <math.h>

#define MAX_RAYS 65536
__device__ int g_seg[MAX_RAYS + 1];

typedef unsigned long long ull;

// ---- packed f32x2 helpers (Blackwell) -------------------------------------
__device__ __forceinline__ ull f2fma(ull a, ull b, ull c) {
    ull d;
    asm("fma.rn.f32x2 %0, %1, %2, %3;" : "=l"(d) : "l"(a), "l"(b), "l"(c));
    return d;
}
__device__ __forceinline__ ull f2add(ull a, ull b) {
    ull d;
    asm("add.rn.f32x2 %0, %1, %2;" : "=l"(d) : "l"(a), "l"(b));
    return d;
}
__device__ __forceinline__ ull f2pack(float lo, float hi) {
    ull d;
    asm("mov.b64 %0, {%1, %2};" : "=l"(d) : "f"(lo), "f"(hi));
    return d;
}
__device__ __forceinline__ void f2unpack(ull v, float& lo, float& hi) {
    asm("mov.b64 {%0, %1}, %2;" : "=f"(lo), "=f"(hi) : "l"(v));
}
#define ABSMASK 0x7FFFFFFF7FFFFFFFULL

// ---------------------------------------------------------------------------
// Kernel A: segment starts from sorted ray_indices (searchsorted).
// ---------------------------------------------------------------------------
__global__ void seg_boundary_kernel(const int* __restrict__ ri, int S, int n_rays) {
    int i = blockIdx.x * blockDim.x + threadIdx.x;
    if (i >= S) return;
    int r = ri[i];
    int rp = (i == 0) ? -1 : ri[i - 1];
    for (int rr = rp + 1; rr <= r; ++rr) g_seg[rr] = i;
    if (i == S - 1) {
        for (int rr = r + 1; rr <= n_rays; ++rr) g_seg[rr] = S;
    }
}

// ---------------------------------------------------------------------------
// Kernel B: one warp per ray; MLP collapsed to 1-D function of t per ray.
//   x_j(t) = a_j t + c_j ;  w2_j relu(x_j) = y_j + sign(w2_j)|y_j|,
//   y_j = (0.5 w2_j a_j) t + (0.5 w2_j c_j).
//   Sum_j y_j = A t + C (per-ray precompute; C absorbs b2).
//   acc(t) = A t + C + Sum_j sign(w2_j)|y_j|
//   sign apply: (y & ABSMASK) ^ M with M = signbit(w2)<<31 per packed half.
// ---------------------------------------------------------------------------
__global__ void __launch_bounds__(256, 3) render_kernel(
    const float* __restrict__ rays_o,
    const float* __restrict__ rays_d,
    const float* __restrict__ W1,
    const float* __restrict__ b1,
    const float* __restrict__ W2,
    const float* __restrict__ b2,
    const float* __restrict__ t_starts,
    const float* __restrict__ t_ends,
    float* __restrict__ out,
    int n_rays)
{
    __shared__ ulonglong2 sCoef[8][32];   // per-warp {a''2, c''2} per pair
    __shared__ ull        sMask[32];      // per-block sign masks (ray-indep)

    const int wlocal  = threadIdx.x >> 5;
    const int lane    = threadIdx.x & 31;
    const int warp_id = (blockIdx.x * blockDim.x + threadIdx.x) >> 5;

    if (threadIdx.x < 32) {
        const int j = 2 * threadIdx.x;
        const unsigned m0 = __float_as_uint(__ldg(&W2[j]))     & 0x80000000u;
        const unsigned m1 = __float_as_uint(__ldg(&W2[j + 1])) & 0x80000000u;
        sMask[threadIdx.x] = ((ull)m1 << 32) | (ull)m0;
    }
    __syncthreads();

    if (warp_id >= n_rays) return;
    const int r = warp_id;

    const int start = g_seg[r];
    const int end   = g_seg[r + 1];

    const float ox = __ldg(&rays_o[3 * r    ]);
    const float oy = __ldg(&rays_o[3 * r + 1]);
    const float oz = __ldg(&rays_o[3 * r + 2]);
    const float dx = __ldg(&rays_d[3 * r    ]);
    const float dy = __ldg(&rays_d[3 * r + 1]);
    const float dz = __ldg(&rays_d[3 * r + 2]);

    // ---- per-ray coefficient precompute (lane p -> units 2p, 2p+1) --------
    float A, C;
    {
        const int j = 2 * lane;
        const float w1x0 = __ldg(&W1[j]),       w1x1 = __ldg(&W1[j + 1]);
        const float w1y0 = __ldg(&W1[64 + j]),  w1y1 = __ldg(&W1[64 + j + 1]);
        const float w1z0 = __ldg(&W1[128 + j]), w1z1 = __ldg(&W1[128 + j + 1]);
        const float b10  = __ldg(&b1[j]),       b11  = __ldg(&b1[j + 1]);
        const float hw0  = 0.5f * __ldg(&W2[j]);
        const float hw1  = 0.5f * __ldg(&W2[j + 1]);

        float a0 = fmaf(dx, w1x0, fmaf(dy, w1y0, dz * w1z0));
        float a1 = fmaf(dx, w1x1, fmaf(dy, w1y1, dz * w1z1));
        float c0 = fmaf(ox, w1x0, fmaf(oy, w1y0, fmaf(oz, w1z0, b10)));
        float c1 = fmaf(ox, w1x1, fmaf(oy, w1y1, fmaf(oz, w1z1, b11)));
        a0 *= hw0; a1 *= hw1; c0 *= hw0; c1 *= hw1;

        ulonglong2 P;
        P.x = f2pack(a0, a1);
        P.y = f2pack(c0, c1);
        sCoef[wlocal][lane] = P;

        float Ap = a0 + a1;
        float Cp = c0 + c1;
        #pragma unroll
        for (int off = 16; off; off >>= 1) {
            Ap += __shfl_xor_sync(0xffffffffu, Ap, off);
            Cp += __shfl_xor_sync(0xffffffffu, Cp, off);
        }
        A = Ap;
        C = Cp + __ldg(b2);
    }
    __syncwarp();

    float carry = 0.f;
    float opac  = 0.f;
    float dnum  = 0.f;

    for (int i0 = start; i0 < end; i0 += 32) {
        const int  i     = i0 + lane;
        const bool valid = (i < end);
        const int  ic    = valid ? i : (end - 1);

        const float ts = t_starts[ic];
        const float te = t_ends[ic];
        const float tm = 0.5f * (ts + te);
        const float dt = te - ts;
        const ull   t2 = f2pack(tm, tm);

        ull acc0 = 0ull, acc1 = 0ull;
        #pragma unroll 8
        for (int p = 0; p < 32; p += 2) {
            const ulonglong2 P0 = sCoef[wlocal][p];
            const ull M0 = sMask[p];
            const ull y0 = f2fma(t2, P0.x, P0.y);
            acc0 = f2add(acc0, (y0 & ABSMASK) ^ M0);   // sign(w2)*|y|
            const ulonglong2 P1 = sCoef[wlocal][p + 1];
            const ull M1 = sMask[p + 1];
            const ull y1 = f2fma(t2, P1.x, P1.y);
            acc1 = f2add(acc1, (y1 & ABSMASK) ^ M1);
        }
        float lo, hi;
        f2unpack(f2add(acc0, acc1), lo, hi);
        const float acc = fmaf(A, tm, C) + lo + hi;

        // softplus(x) = max(x,0) + log(1 + exp(-|x|))
        const float sp = fmaxf(acc, 0.f) + __logf(1.f + __expf(-fabsf(acc)));
        const float s  = valid ? sp * dt : 0.f;

        // warp-inclusive scan of s
        float incl = s;
        #pragma unroll
        for (int off = 1; off < 32; off <<= 1) {
            float v = __shfl_up_sync(0xffffffffu, incl, off);
            if (lane >= off) incl += v;
        }
        const float excl = incl - s;

        // invalid lanes: s==0 -> w==0 exactly
        const float w = __expf(-(carry + excl)) * (-expm1f(-s));
        opac += w;
        dnum  = fmaf(w, tm, dnum);
        carry += __shfl_sync(0xffffffffu, incl, 31);
    }

    #pragma unroll
    for (int off = 16; off; off >>= 1) {
        opac += __shfl_xor_sync(0xffffffffu, opac, off);
        dnum += __shfl_xor_sync(0xffffffffu, dnum, off);
    }

    if (lane == 0) {
        const float depth = dnum / fmaxf(opac, 1.17549435e-38f);
        out[2 * r    ] = opac;
        out[2 * r + 1] = depth;
    }
}

extern "C" void kernel_launch(void* const* d_in, const int* in_sizes, int n_in,
                              void* d_out, int out_size) {
    const float* rays_o      = (const float*)d_in[0];
    const float* rays_d      = (const float*)d_in[1];
    const float* W1          = (const float*)d_in[2];
    const float* b1          = (const float*)d_in[3];
    const float* W2          = (const float*)d_in[4];
    const float* b2          = (const float*)d_in[5];
    const float* t_starts    = (const float*)d_in[6];
    const float* t_ends      = (const float*)d_in[7];
    const int*   ray_indices = (const int*)d_in[8];

    const int S      = in_sizes[6];
    const int n_rays = in_sizes[0] / 3;

    float* out = (float*)d_out;

    seg_boundary_kernel<<<(S + 255) / 256, 256>>>(ray_indices, S, n_rays);

    const int warps_per_block = 8;
    const int blocks = (n_rays + warps_per_block - 1) / warps_per_block;
    render_kernel<<<blocks, warps_per_block * 32>>>(
        rays_o, rays_d, W1, b1, W2, b2, t_starts, t_ends, out, n_rays);
}

// round 6
// speedup vs baseline: 3.6903x; 1.2240x over previous
#include <cuda_runtime.h>
#include <math.h>

#define MAX_RAYS 65536
__device__ int g_seg[MAX_RAYS + 1];

// sign-grouped weights (built by kernel A, consumed by kernel B)
__device__ float4 gPW[64];    // {w1x, w1y, w1z, b1} per grouped unit
__device__ float  gMA[64];    // |0.5*w2|
__device__ float  gMS[64];    // 0.5*w2 (signed, for linear part)
__device__ int    gPosTotal;  // # units with w2 >= 0

typedef unsigned long long ull;

// ---- packed f32x2 helpers (Blackwell) -------------------------------------
__device__ __forceinline__ ull f2fma(ull a, ull b, ull c) {
    ull d;
    asm("fma.rn.f32x2 %0, %1, %2, %3;" : "=l"(d) : "l"(a), "l"(b), "l"(c));
    return d;
}
__device__ __forceinline__ ull f2add(ull a, ull b) {
    ull d;
    asm("add.rn.f32x2 %0, %1, %2;" : "=l"(d) : "l"(a), "l"(b));
    return d;
}
__device__ __forceinline__ ull f2pack(float lo, float hi) {
    ull d;
    asm("mov.b64 %0, {%1, %2};" : "=l"(d) : "f"(lo), "f"(hi));
    return d;
}
__device__ __forceinline__ void f2unpack(ull v, float& lo, float& hi) {
    asm("mov.b64 {%0, %1}, %2;" : "=f"(lo), "=f"(hi) : "l"(v));
}
#define ABSMASK 0x7FFFFFFF7FFFFFFFULL
#define HISIGN  0x8000000000000000ULL

// ---------------------------------------------------------------------------
// Kernel A: (a) block 0 builds the sign-grouped weight permutation,
//           (b) all blocks build segment starts from sorted ray_indices.
// ---------------------------------------------------------------------------
__global__ void seg_boundary_kernel(const int* __restrict__ ri, int S, int n_rays,
                                    const float* __restrict__ W1,
                                    const float* __restrict__ b1,
                                    const float* __restrict__ W2) {
    if (blockIdx.x == 0) {
        __shared__ int sPosCnt[2];
        const int t = threadIdx.x;
        const bool active = (t < 64);
        const float w2 = active ? W2[t] : 0.f;
        const bool pz = active && (w2 >= 0.f);
        const unsigned b = __ballot_sync(0xffffffffu, pz);
        if (active && (t & 31) == 0) sPosCnt[t >> 5] = __popc(b);
        __syncthreads();
        if (active) {
            const int lane = t & 31, w = t >> 5;
            const unsigned mlt = (1u << lane) - 1u;
            const int prefPos = __popc(b & mlt);
            const int prefNeg = lane - prefPos;
            const int posTotal = sPosCnt[0] + sPosCnt[1];
            int idx;
            if (pz) idx = (w ? sPosCnt[0] : 0) + prefPos;
            else    idx = posTotal + (w ? (32 - sPosCnt[0]) : 0) + prefNeg;
            gPW[idx] = make_float4(W1[t], W1[64 + t], W1[128 + t], b1[t]);
            const float m = 0.5f * w2;
            gMA[idx] = fabsf(m);
            gMS[idx] = m;
            if (t == 0) gPosTotal = posTotal;
        }
    }

    const int i = blockIdx.x * blockDim.x + threadIdx.x;
    if (i >= S) return;
    const int r = ri[i];
    const int rp = (i == 0) ? -1 : ri[i - 1];
    for (int rr = rp + 1; rr <= r; ++rr) g_seg[rr] = i;
    if (i == S - 1) {
        for (int rr = r + 1; rr <= n_rays; ++rr) g_seg[rr] = S;
    }
}

// ---------------------------------------------------------------------------
// Kernel B: one warp per ray; MLP collapsed to 1-D function of t:
//   acc(t) = A t + C + Sum_pos |u t + v| - Sum_neg |u t + v|
//   with (u,v) = |0.5 w2| * (a, c), a = d.W1_j, c = o.W1_j + b1_j.
// Units sign-grouped, so inner loop needs NO per-pair sign mask:
//   1 LDS.128 + FFMA2 + 2 LOP3 + FADD2 per packed pair.
// ---------------------------------------------------------------------------
__global__ void __launch_bounds__(256, 4) render_kernel(
    const float* __restrict__ rays_o,
    const float* __restrict__ rays_d,
    const float* __restrict__ b2,
    const float* __restrict__ t_starts,
    const float* __restrict__ t_ends,
    float* __restrict__ out,
    int n_rays)
{
    __shared__ ulonglong2 sPC[8][32];   // per-warp {u2, v2} per pair

    const int wlocal  = threadIdx.x >> 5;
    const int lane    = threadIdx.x & 31;
    const int warp_id = (blockIdx.x * blockDim.x + threadIdx.x) >> 5;
    if (warp_id >= n_rays) return;
    const int r = warp_id;

    const int start = g_seg[r];
    const int end   = g_seg[r + 1];

    const float ox = __ldg(&rays_o[3 * r    ]);
    const float oy = __ldg(&rays_o[3 * r + 1]);
    const float oz = __ldg(&rays_o[3 * r + 2]);
    const float dx = __ldg(&rays_d[3 * r    ]);
    const float dy = __ldg(&rays_d[3 * r + 1]);
    const float dz = __ldg(&rays_d[3 * r + 2]);

    // ---- per-ray coefficient precompute (lane p -> grouped units 2p,2p+1) -
    float A, C;
    {
        const int j = 2 * lane;
        const float4 q0 = gPW[j];
        const float4 q1 = gPW[j + 1];
        const float ma0 = gMA[j], ma1 = gMA[j + 1];
        const float ms0 = gMS[j], ms1 = gMS[j + 1];

        const float a0 = fmaf(dx, q0.x, fmaf(dy, q0.y, dz * q0.z));
        const float a1 = fmaf(dx, q1.x, fmaf(dy, q1.y, dz * q1.z));
        const float c0 = fmaf(ox, q0.x, fmaf(oy, q0.y, fmaf(oz, q0.z, q0.w)));
        const float c1 = fmaf(ox, q1.x, fmaf(oy, q1.y, fmaf(oz, q1.z, q1.w)));

        ulonglong2 P;
        P.x = f2pack(ma0 * a0, ma1 * a1);
        P.y = f2pack(ma0 * c0, ma1 * c1);
        sPC[wlocal][lane] = P;

        float Ap = fmaf(ms0, a0, ms1 * a1);
        float Cp = fmaf(ms0, c0, ms1 * c1);
        #pragma unroll
        for (int off = 16; off; off >>= 1) {
            Ap += __shfl_xor_sync(0xffffffffu, Ap, off);
            Cp += __shfl_xor_sync(0xffffffffu, Cp, off);
        }
        A = Ap;
        C = Cp + __ldg(b2);
    }
    __syncwarp();

    const int posTotal = gPosTotal;      // warp-uniform
    const int P2  = posTotal >> 1;
    const int mix = posTotal & 1;
    const ulonglong2* pc = sPC[wlocal];

    float carry = 0.f;
    float opac  = 0.f;
    float dnum  = 0.f;

    for (int i0 = start; i0 < end; i0 += 32) {
        const int  i     = i0 + lane;
        const bool valid = (i < end);
        const int  ic    = valid ? i : (end - 1);

        const float ts = t_starts[ic];
        const float te = t_ends[ic];
        const float tm = 0.5f * (ts + te);
        const float dt = te - ts;
        const ull   t2 = f2pack(tm, tm);

        ull accP = 0ull, accN = 0ull;
        int p = 0;
        #pragma unroll 8
        for (; p < P2; ++p) {
            const ulonglong2 Q = pc[p];
            const ull y = f2fma(t2, Q.x, Q.y);
            accP = f2add(accP, y & ABSMASK);
        }
        if (mix) {
            const ulonglong2 Q = pc[P2];
            const ull y = f2fma(t2, Q.x, Q.y);
            accP = f2add(accP, (y & ABSMASK) ^ HISIGN);  // lo=+, hi=-
        }
        #pragma unroll 8
        for (int q = P2 + mix; q < 32; ++q) {
            const ulonglong2 Q = pc[q];
            const ull y = f2fma(t2, Q.x, Q.y);
            accN = f2add(accN, y & ABSMASK);
        }

        float pl, ph, nl, nh;
        f2unpack(accP, pl, ph);
        f2unpack(accN, nl, nh);
        const float acc = fmaf(A, tm, C) + (pl + ph) - (nl + nh);

        // softplus(x) = max(x,0) + log(1 + exp(-|x|))
        const float sp = fmaxf(acc, 0.f) + __logf(1.f + __expf(-fabsf(acc)));
        const float s  = valid ? sp * dt : 0.f;

        // warp-inclusive scan of s
        float incl = s;
        #pragma unroll
        for (int off = 1; off < 32; off <<= 1) {
            float v = __shfl_up_sync(0xffffffffu, incl, off);
            if (lane >= off) incl += v;
        }
        const float excl = incl - s;

        // w = trans*alpha = e^{-(carry+excl)} - e^{-(carry+incl)}; 0 when s==0
        const float w = __expf(-(carry + excl)) - __expf(-(carry + incl));
        opac += w;
        dnum  = fmaf(w, tm, dnum);
        carry += __shfl_sync(0xffffffffu, incl, 31);
    }

    #pragma unroll
    for (int off = 16; off; off >>= 1) {
        opac += __shfl_xor_sync(0xffffffffu, opac, off);
        dnum += __shfl_xor_sync(0xffffffffu, dnum, off);
    }

    if (lane == 0) {
        const float depth = dnum / fmaxf(opac, 1.17549435e-38f);
        out[2 * r    ] = opac;
        out[2 * r + 1] = depth;
    }
}

extern "C" void kernel_launch(void* const* d_in, const int* in_sizes, int n_in,
                              void* d_out, int out_size) {
    const float* rays_o      = (const float*)d_in[0];
    const float* rays_d      = (const float*)d_in[1];
    const float* W1          = (const float*)d_in[2];
    const float* b1          = (const float*)d_in[3];
    const float* W2          = (const float*)d_in[4];
    const float* b2          = (const float*)d_in[5];
    const float* t_starts    = (const float*)d_in[6];
    const float* t_ends      = (const float*)d_in[7];
    const int*   ray_indices = (const int*)d_in[8];

    const int S      = in_sizes[6];
    const int n_rays = in_sizes[0] / 3;

    float* out = (float*)d_out;

    seg_boundary_kernel<<<(S + 255) / 256, 256>>>(ray_indices, S, n_rays, W1, b1, W2);

    const int warps_per_block = 8;
    const int blocks = (n_rays + warps_per_block - 1) / warps_per_block;
    render_kernel<<<blocks, warps_per_block * 32>>>(
        rays_o, rays_d, b2, t_starts, t_ends, out, n_rays);
}